// round 14
// baseline (speedup 1.0000x reference)
#include <cuda_runtime.h>
#include <stdint.h>
#include <math.h>

// Problem shape (fixed by the reference's setup_inputs)
#define Bn 4
#define Tn 8192
#define Dn 1024
#define D4n (Dn / 4)       // 256 float4 groups across channels
#define Ln 32              // chunk length along time
#define Cn (Tn / Ln)       // 256 chunks
#define CPL 8              // chunks per lane in the warp scan
#define NIT (Cn * Bn * D4n)    // 262144 work items == threads (1 chunk/thread)
#define NSCAN (Bn * Dn * 32)   // 131072 threads participate in phase2
#define GRID_CTAS (NIT / 256)  // 1024 CTAs; 8/SM co-resident (smem 0, regs<=128)

// Scan tables, computed in-kernel (double closed form) by table-duty threads:
__device__ float2 g_rL[Dn];      // r^L
__device__ float2 g_w [5][Dn];   // r^(8L * 2^s), s = 0..4

// Scratch (L2-resident): chunk-end and carry-in states, [c][b][k][d4]. 8 MB each.
__device__ float2 g_ends [Cn * Bn * 4 * D4n];
__device__ float2 g_carry[Cn * Bn * 4 * D4n];

// Self-resetting ticket barrier (never reset; correct across graph replays).
__device__ unsigned g_bar[2];

// ---------------------------------------------------------------------------
__device__ __forceinline__ void gsync(int slot)
{
    __syncthreads();
    if (threadIdx.x == 0) {
        __threadfence();                               // release prior writes
        unsigned ticket = atomicAdd(&g_bar[slot], 1u);
        unsigned target = (ticket / GRID_CTAS + 1u) * GRID_CTAS;
        volatile unsigned* bp = &g_bar[slot];
        while (*bp < target) { }
        __threadfence();                               // acquire
    }
    __syncthreads();
}

// ---------------------------------------------------------------------------
// Single fused kernel, full-occupancy grid (1024 CTAs co-resident @ 8/SM):
//   phase1: local recurrence, one chunk per thread (x streamed, ends out)
//   table duty after phase1 (hides in barrier slack): doubles -> g_rL / g_w
//   gsync | phase2: warp-parallel Kogge-Stone scan (first 131072 threads) |
//   gsync | phase3: replay with carry (own x re-read mostly L2-hot), write y
// ---------------------------------------------------------------------------
__global__ __launch_bounds__(256, 8)
void k_fused(const float4* __restrict__ x, float4* __restrict__ y,
             const float* __restrict__ decay, const float* __restrict__ freq)
{
    const int t = blockIdx.x * blockDim.x + threadIdx.x;

    // item decomposition: one (c, b, d4) chunk per thread
    const int d4 = t % D4n;
    const int b  = (t / D4n) % Bn;
    const int c  = t / (D4n * Bn);

    // ---- per-thread step rotation r for 4 channels (fp32 closed form) ----
    float rre[4], rim[4];
    {
        const float4* a4p = (const float4*)decay;
        const float4* f4p = (const float4*)freq;
        float4 a4 = a4p[d4];
        float4 f4 = f4p[d4];
        float av[4] = {a4.x, a4.y, a4.z, a4.w};
        float fv[4] = {f4.x, f4.y, f4.z, f4.w};
#pragma unroll
        for (int k = 0; k < 4; k++) {
            float g = expf(-fabsf(av[k]));
            float s, co;
            sincosf(fv[k], &s, &co);
            rre[k] = g * co;
            rim[k] = g * s;
        }
    }

    const float4* xp = x + (size_t)(b * Tn + c * Ln) * D4n + d4;
    float4*       yp = y + (size_t)(b * Tn + c * Ln) * D4n + d4;

    // ---------------- phase 1: local recurrence, zero init ----------------
    {
        float zre[4] = {0.f, 0.f, 0.f, 0.f};
        float zim[4] = {0.f, 0.f, 0.f, 0.f};
#pragma unroll 8
        for (int j = 0; j < Ln; j++) {
            float4 xv = xp[(size_t)j * D4n];
            float xr[4] = {xv.x, xv.y, xv.z, xv.w};
#pragma unroll
            for (int k = 0; k < 4; k++) {
                float nre = fmaf(rre[k], zre[k], fmaf(-rim[k], zim[k], xr[k]));
                float nim = fmaf(rre[k], zim[k], rim[k] * zre[k]);
                zre[k] = nre;
                zim[k] = nim;
            }
        }
#pragma unroll
        for (int k = 0; k < 4; k++)
            g_ends[((c * Bn + b) * 4 + k) * D4n + d4] =
                make_float2(zre[k], zim[k]);
    }

    // ---- table duty AFTER phase1: FP64 hides in barrier-wait slack ----
    if (t < 6 * Dn) {
        int d = t % Dn;
        int j = t / Dn;                       // 0 -> rL, 1..5 -> w[j-1]
        double span = (j == 0) ? (double)Ln
                               : (double)(CPL * Ln * (1 << (j - 1)));
        double a = fabs((double)decay[d]);
        double f = (double)freq[d];
        double g = exp(-a * span);
        float2 v = make_float2((float)(g * cos(f * span)),
                               (float)(g * sin(f * span)));
        if (j == 0) g_rL[d] = v;
        else        g_w[j - 1][d] = v;
    }

    gsync(0);

    // ------- phase 2: warp-parallel scan over chunks (first NSCAN threads) -------
    if (t < NSCAN) {
        const int wid  = t >> 5;         // 0 .. Bn*Dn-1  (4096 series)
        const int lane = t & 31;
        const int d  = wid % Dn;
        const int sb = wid / Dn;
        const int sd4 = d >> 2;
        const int sk  = d & 3;

        float2 rL = g_rL[d];
        float rLre = rL.x, rLim = rL.y;

        float2 e[CPL];
        float Are = 0.0f, Aim = 0.0f;
#pragma unroll
        for (int i = 0; i < CPL; i++) {
            int cc = lane * CPL + i;
            e[i] = g_ends[((cc * Bn + sb) * 4 + sk) * D4n + sd4];
            float nre = fmaf(rLre, Are, fmaf(-rLim, Aim, e[i].x));
            float nim = fmaf(rLre, Aim, fmaf(rLim, Are, e[i].y));
            Are = nre; Aim = nim;
        }

        float Sre = Are, Sim = Aim;
#pragma unroll
        for (int step = 0; step < 5; step++) {
            int off = 1 << step;
            float2 w = g_w[step][d];
            float Pre = __shfl_up_sync(0xFFFFFFFFu, Sre, off);
            float Pim = __shfl_up_sync(0xFFFFFFFFu, Sim, off);
            if (lane >= off) {
                Sre = fmaf(w.x, Pre, fmaf(-w.y, Pim, Sre));
                Sim = fmaf(w.x, Pim, fmaf(w.y, Pre, Sim));
            }
        }

        float Cre = __shfl_up_sync(0xFFFFFFFFu, Sre, 1);
        float Cim = __shfl_up_sync(0xFFFFFFFFu, Sim, 1);
        if (lane == 0) { Cre = 0.0f; Cim = 0.0f; }

#pragma unroll
        for (int i = 0; i < CPL; i++) {
            int cc = lane * CPL + i;
            g_carry[((cc * Bn + sb) * 4 + sk) * D4n + sd4] =
                make_float2(Cre, Cim);
            float nre = fmaf(rLre, Cre, fmaf(-rLim, Cim, e[i].x));
            float nim = fmaf(rLre, Cim, fmaf(rLim, Cre, e[i].y));
            Cre = nre; Cim = nim;
        }
    }

    gsync(1);

    // -------- phase 3: replay with carry; own x re-read is mostly L2-hot --------
    {
        float zre[4], zim[4];
#pragma unroll
        for (int k = 0; k < 4; k++) {
            float2 cc = g_carry[((c * Bn + b) * 4 + k) * D4n + d4];
            zre[k] = cc.x;
            zim[k] = cc.y;
        }
#pragma unroll 8
        for (int j = 0; j < Ln; j++) {
            float4 xv = xp[(size_t)j * D4n];
            float xr[4] = {xv.x, xv.y, xv.z, xv.w};
#pragma unroll
            for (int k = 0; k < 4; k++) {
                float nre = fmaf(rre[k], zre[k], fmaf(-rim[k], zim[k], xr[k]));
                float nim = fmaf(rre[k], zim[k], rim[k] * zre[k]);
                zre[k] = nre;
                zim[k] = nim;
            }
            __stcs(&yp[(size_t)j * D4n],
                   make_float4(zre[0], zre[1], zre[2], zre[3]));
        }
    }
}

// ---------------------------------------------------------------------------
extern "C" void kernel_launch(void* const* d_in, const int* in_sizes, int n_in,
                              void* d_out, int out_size)
{
    const float* x     = (const float*)d_in[0];
    const float* decay = (const float*)d_in[1];
    const float* freq  = (const float*)d_in[2];
    float* y = (float*)d_out;

    k_fused<<<GRID_CTAS, 256>>>((const float4*)x, (float4*)y, decay, freq);
}

// round 15
// speedup vs baseline: 1.2570x; 1.2570x over previous
#include <cuda_runtime.h>
#include <stdint.h>
#include <math.h>

// Problem shape (fixed by the reference's setup_inputs)
#define Bn 4
#define Tn 8192
#define Dn 1024
#define D4n (Dn / 4)       // 256 float4 groups across channels
#define Ln 32              // chunk length along time
#define Cn (Tn / Ln)       // 256 chunks
#define CPL 8              // chunks per lane in the warp scan
#define TPB 256
#define GRID_CTAS 512          // 131072 threads; 4 CTAs/SM co-resident
#define GROUP_CTAS 128         // CTAs per batch group (512 / Bn)
#define TPG 32768              // threads per batch group

// Scan tables (double closed form, written redundantly by each batch group —
// identical values, benign race):
__device__ float2 g_rL[Dn];      // r^L
__device__ float2 g_w [5][Dn];   // r^(8L * 2^s), s = 0..4

// Scratch (L2-resident): chunk-end and carry-in states, [c][b][k][d4]. 8 MB each.
__device__ float2 g_ends [Cn * Bn * 4 * D4n];
__device__ float2 g_carry[Cn * Bn * 4 * D4n];

// Self-resetting ticket barriers: 2 per batch group (8 slots).
__device__ unsigned g_bar[8];

// ---------------------------------------------------------------------------
__device__ __forceinline__ void gsync_group(int slot)
{
    __syncthreads();
    if (threadIdx.x == 0) {
        __threadfence();                               // release prior writes
        unsigned ticket = atomicAdd(&g_bar[slot], 1u);
        unsigned target = (ticket / GROUP_CTAS + 1u) * GROUP_CTAS;
        volatile unsigned* bp = &g_bar[slot];
        while (*bp < target) { }
        __threadfence();                               // acquire
    }
    __syncthreads();
}

// ---------------------------------------------------------------------------
// Fused, per-batch pipelined:
//   item order [b][c][d4]; batch b owned by CTA group b (128 CTAs).
//   phase1 (2 rounds: c0, c0+128) -> batch x becomes L2-resident (33.5 MB)
//   table duty (redundant per group) -> group barrier
//   phase2: warp scan, one warp per channel d of this batch -> group barrier
//   phase3 (rounds reversed): replay with carry; x re-read ~all L2-hot.
// Groups pipeline: other batches keep streaming while one batch syncs/scans.
// ---------------------------------------------------------------------------
__global__ __launch_bounds__(TPB, 4)
void k_fused(const float4* __restrict__ x, float4* __restrict__ y,
             const float* __restrict__ decay, const float* __restrict__ freq)
{
    const int t  = blockIdx.x * TPB + threadIdx.x;
    const int b  = t >> 15;           // batch = group id (32768 threads each)
    const int tl = t & (TPG - 1);     // thread index within group
    const int d4 = tl & (D4n - 1);    // channel group
    const int c0 = tl >> 8;           // 0..127 (chunk base; rounds add 0/128)

    // ---- per-thread step rotation r for 4 channels (fp32 closed form) ----
    float rre[4], rim[4];
    {
        const float4* a4p = (const float4*)decay;
        const float4* f4p = (const float4*)freq;
        float4 a4 = a4p[d4];
        float4 f4 = f4p[d4];
        float av[4] = {a4.x, a4.y, a4.z, a4.w};
        float fv[4] = {f4.x, f4.y, f4.z, f4.w};
#pragma unroll
        for (int k = 0; k < 4; k++) {
            float g = expf(-fabsf(av[k]));
            float s, co;
            sincosf(fv[k], &s, &co);
            rre[k] = g * co;
            rim[k] = g * s;
        }
    }

    // ---------------- phase 1: local recurrence, rounds c0, c0+128 ----------------
#pragma unroll 1
    for (int r = 0; r < 2; r++) {
        const int c = c0 + r * (Cn / 2);
        const float4* xp = x + (size_t)(b * Tn + c * Ln) * D4n + d4;

        float zre[4] = {0.f, 0.f, 0.f, 0.f};
        float zim[4] = {0.f, 0.f, 0.f, 0.f};
#pragma unroll 8
        for (int j = 0; j < Ln; j++) {
            float4 xv = xp[(size_t)j * D4n];
            float xr[4] = {xv.x, xv.y, xv.z, xv.w};
#pragma unroll
            for (int k = 0; k < 4; k++) {
                float nre = fmaf(rre[k], zre[k], fmaf(-rim[k], zim[k], xr[k]));
                float nim = fmaf(rre[k], zim[k], rim[k] * zre[k]);
                zre[k] = nre;
                zim[k] = nim;
            }
        }
#pragma unroll
        for (int k = 0; k < 4; k++)
            g_ends[((c * Bn + b) * 4 + k) * D4n + d4] =
                make_float2(zre[k], zim[k]);
    }

    // ---- table duty (after phase1; redundant per group, identical values) ----
    if (tl < 6 * Dn) {
        int d = tl % Dn;
        int j = tl / Dn;                       // 0 -> rL, 1..5 -> w[j-1]
        double span = (j == 0) ? (double)Ln
                               : (double)(CPL * Ln * (1 << (j - 1)));
        double a = fabs((double)decay[d]);
        double f = (double)freq[d];
        double g = exp(-a * span);
        float2 v = make_float2((float)(g * cos(f * span)),
                               (float)(g * sin(f * span)));
        if (j == 0) g_rL[d] = v;
        else        g_w[j - 1][d] = v;
    }

    gsync_group(2 * b);

    // ------- phase 2: warp scan; one warp per channel d of this batch -------
    {
        const int d    = tl >> 5;        // 0..1023
        const int lane = tl & 31;
        const int sd4 = d >> 2;
        const int sk  = d & 3;

        float2 rL = g_rL[d];
        float rLre = rL.x, rLim = rL.y;

        float2 e[CPL];
        float Are = 0.0f, Aim = 0.0f;
#pragma unroll
        for (int i = 0; i < CPL; i++) {
            int cc = lane * CPL + i;
            e[i] = g_ends[((cc * Bn + b) * 4 + sk) * D4n + sd4];
            float nre = fmaf(rLre, Are, fmaf(-rLim, Aim, e[i].x));
            float nim = fmaf(rLre, Aim, fmaf(rLim, Are, e[i].y));
            Are = nre; Aim = nim;
        }

        float Sre = Are, Sim = Aim;
#pragma unroll
        for (int step = 0; step < 5; step++) {
            int off = 1 << step;
            float2 w = g_w[step][d];
            float Pre = __shfl_up_sync(0xFFFFFFFFu, Sre, off);
            float Pim = __shfl_up_sync(0xFFFFFFFFu, Sim, off);
            if (lane >= off) {
                Sre = fmaf(w.x, Pre, fmaf(-w.y, Pim, Sre));
                Sim = fmaf(w.x, Pim, fmaf(w.y, Pre, Sim));
            }
        }

        float Cre = __shfl_up_sync(0xFFFFFFFFu, Sre, 1);
        float Cim = __shfl_up_sync(0xFFFFFFFFu, Sim, 1);
        if (lane == 0) { Cre = 0.0f; Cim = 0.0f; }

#pragma unroll
        for (int i = 0; i < CPL; i++) {
            int cc = lane * CPL + i;
            g_carry[((cc * Bn + b) * 4 + sk) * D4n + sd4] =
                make_float2(Cre, Cim);
            float nre = fmaf(rLre, Cre, fmaf(-rLim, Cim, e[i].x));
            float nim = fmaf(rLre, Cim, fmaf(rLim, Cre, e[i].y));
            Cre = nre; Cim = nim;
        }
    }

    gsync_group(2 * b + 1);

    // -------- phase 3: replay with carry; batch x re-read is L2-hot --------
#pragma unroll 1
    for (int r = 1; r >= 0; r--) {
        const int c = c0 + r * (Cn / 2);

        float zre[4], zim[4];
#pragma unroll
        for (int k = 0; k < 4; k++) {
            float2 cc = g_carry[((c * Bn + b) * 4 + k) * D4n + d4];
            zre[k] = cc.x;
            zim[k] = cc.y;
        }

        const float4* xp = x + (size_t)(b * Tn + c * Ln) * D4n + d4;
        float4*       yp = y + (size_t)(b * Tn + c * Ln) * D4n + d4;
#pragma unroll 8
        for (int j = 0; j < Ln; j++) {
            float4 xv = xp[(size_t)j * D4n];
            float xr[4] = {xv.x, xv.y, xv.z, xv.w};
#pragma unroll
            for (int k = 0; k < 4; k++) {
                float nre = fmaf(rre[k], zre[k], fmaf(-rim[k], zim[k], xr[k]));
                float nim = fmaf(rre[k], zim[k], rim[k] * zre[k]);
                zre[k] = nre;
                zim[k] = nim;
            }
            __stcs(&yp[(size_t)j * D4n],
                   make_float4(zre[0], zre[1], zre[2], zre[3]));
        }
    }
}

// ---------------------------------------------------------------------------
extern "C" void kernel_launch(void* const* d_in, const int* in_sizes, int n_in,
                              void* d_out, int out_size)
{
    const float* x     = (const float*)d_in[0];
    const float* decay = (const float*)d_in[1];
    const float* freq  = (const float*)d_in[2];
    float* y = (float*)d_out;

    k_fused<<<GRID_CTAS, TPB>>>((const float4*)x, (float4*)y, decay, freq);
}